// round 12
// baseline (speedup 1.0000x reference)
#include <cuda_runtime.h>
#include <float.h>

#define BT     (16 * 512)   // 8192 pairs
#define IDIM   80
#define HDIM   512
#define NSHIFT 159
#define PAD    79
#define SKP    248          // keypad floats (even; float2-viewable)

typedef unsigned long long ull;

// Scratch for x_attn (allocation-free rule: __device__ global)
__device__ float g_xattn[BT * IDIM];

__device__ __forceinline__ float warpReduceSum(float v) {
#pragma unroll
    for (int o = 16; o; o >>= 1) v += __shfl_xor_sync(0xffffffffu, v, o);
    return v;
}
__device__ __forceinline__ float warpReduceMax(float v) {
#pragma unroll
    for (int o = 16; o; o >>= 1) v = fmaxf(v, __shfl_xor_sync(0xffffffffu, v, o));
    return v;
}

#define FMA2(D, A, B) \
    asm("fma.rn.f32x2 %0, %1, %2, %0;" : "+l"(D) : "l"(A), "l"(B))

__device__ __forceinline__ float ull_sum2(ull v) {
    float lo, hi;
    asm("mov.b64 {%0, %1}, %2;" : "=f"(lo), "=f"(hi) : "l"(v));
    return lo + hi;
}

// ---------------------------------------------------------------------------
// Kernel 1: warp-per-pair. R12: packed-f32x2 dot loop over i-pairs with
// aligned LDS.64 from dual keypad copies (kpe = even pairs, kpo = odd pairs).
// Shared-core all-positive norm decomposition (R6-validated).
// ---------------------------------------------------------------------------
#define PAIRS_PER_BLK 8
#define WSTRIDE 576   // kp[248] + kpo[248] + ys[80] floats per warp

__global__ __launch_bounds__(256) void attn_kernel(
    const float* __restrict__ x, const float* __restrict__ y,
    float* __restrict__ xattn)
{
    const int warp = threadIdx.x >> 5;
    const int lane = threadIdx.x & 31;
    const int p    = blockIdx.x * PAIRS_PER_BLK + warp;

    __shared__ __align__(16) float smem[PAIRS_PER_BLK][WSTRIDE];
    float* kpw = smem[warp];          // keypad, 248 floats
    float* kpo = kpw + SKP;           // odd-pair copy, 248 floats (123 pairs)
    float* ysw = kpw + 2 * SKP;       // y, 80 floats

    for (int i = lane; i < SKP; i += 32) kpw[i] = 0.0f;
    __syncwarp();

    const float* xp = x + (size_t)p * IDIM;
    const float* yp = y + (size_t)p * IDIM;
    float yn2 = 0.0f;
    for (int i = lane; i < IDIM; i += 32) {
        kpw[PAD + i] = xp[i];
        float v = yp[i];
        ysw[i] = v;
        yn2 = fmaf(v, v, yn2);
    }
    yn2 = warpReduceSum(yn2);
    __syncwarp();

    // Build odd-shifted pair copy: kpo2[m] = (kp[2m+1], kp[2m+2])
    for (int m = lane; m < 123; m += 32) {
        *reinterpret_cast<float2*>(kpo + 2 * m) =
            make_float2(kpw[2 * m + 1], kpw[2 * m + 2]);
    }
    __syncwarp();

    const int base = lane * 5;
    const int h0   = base >> 1;
    const int bo   = base & 1;
    const ull* kpe64 = reinterpret_cast<const ull*>(kpw);
    const ull* kpo64 = reinterpret_cast<const ull*>(kpo);
    const ull* ys64  = reinterpret_cast<const ull*>(ysw);
    const ull* PA = bo ? kpo64 : kpe64;   // pairs for even shifts j=0,2,4
    const ull* PB = bo ? kpe64 : kpo64;   // pairs for odd  shifts j=1,3

    ull A0 = PA[h0], A1 = PA[h0 + 1], A2;
    ull B0 = PB[h0 + bo], B1;
    ull D0 = 0, D1 = 0, D2 = 0, D3 = 0, D4 = 0, C = 0;

#pragma unroll
    for (int m = 0; m < 40; ++m) {
        ull Y = ys64[m];
        A2 = PA[h0 + m + 2];
        B1 = PB[h0 + m + 1 + bo];
        FMA2(D0, A0, Y);
        FMA2(D1, B0, Y);
        FMA2(D2, A1, Y);
        FMA2(D3, B1, Y);
        FMA2(D4, A2, Y);
        if (m < 38) FMA2(C, A2, A2);   // core: kp[base+4 .. base+79]^2
        A0 = A1; A1 = A2;
        B0 = B1;
    }

    float dotv[5];
    dotv[0] = ull_sum2(D0);
    dotv[1] = ull_sum2(D1);
    dotv[2] = ull_sum2(D2);
    dotv[3] = ull_sum2(D3);
    dotv[4] = ull_sum2(D4);
    const float core = ull_sum2(C);

    // head/tail fixups (scalar, exact; R6-validated all-positive scheme)
    const float i0 = kpw[base + 0], i1 = kpw[base + 1],
                i2 = kpw[base + 2], i3 = kpw[base + 3];
    const float t0 = kpw[base + 80], t1 = kpw[base + 81],
                t2 = kpw[base + 82], t3 = kpw[base + 83];
    const float H3 = i3 * i3;
    const float H2 = fmaf(i2, i2, H3);
    const float H1 = fmaf(i1, i1, H2);
    const float H0 = fmaf(i0, i0, H1);
    const float T1 = t0 * t0;
    const float T2 = fmaf(t1, t1, T1);
    const float T3 = fmaf(t2, t2, T2);
    const float T4 = fmaf(t3, t3, T3);

    float n2v[5];
    n2v[0] = H0 + core;
    n2v[1] = (H1 + core) + T1;
    n2v[2] = (H2 + core) + T2;
    n2v[3] = (H3 + core) + T3;
    n2v[4] = core + T4;

    const float yn = sqrtf(yn2);
    float best = -FLT_MAX;
    int   bidx = 0;
#pragma unroll
    for (int j = 0; j < 5; ++j) {
        int s = base + j;
        if (s < NSHIFT) {
            float den = sqrtf(n2v[j]) * yn;
            float sim = (den > 0.0f) ? (dotv[j] / den) : 0.0f;
            if (sim > best) { best = sim; bidx = s; }
        }
    }
#pragma unroll
    for (int o = 16; o; o >>= 1) {
        float ov = __shfl_xor_sync(0xffffffffu, best, o);
        int   oi = __shfl_xor_sync(0xffffffffu, bidx, o);
        if (ov > best || (ov == best && oi < bidx)) { best = ov; bidx = oi; }
    }
    const int bs = bidx;

    float xa[3], sc[3];
    float m = -FLT_MAX;
#pragma unroll
    for (int t = 0; t < 3; ++t) {
        int i = lane + t * 32;
        if (i < IDIM) {
            xa[t] = kpw[bs + i];
            sc[t] = xa[t] * ysw[i];
            m = fmaxf(m, sc[t]);
        }
    }
    m = warpReduceMax(m);
    float sum = 0.0f, e[3];
#pragma unroll
    for (int t = 0; t < 3; ++t) {
        int i = lane + t * 32;
        if (i < IDIM) { e[t] = expf((sc[t] - m) * 0.1f); sum += e[t]; }
    }
    sum = warpReduceSum(sum);
    const float inv = 1.0f / sum;
#pragma unroll
    for (int t = 0; t < 3; ++t) {
        int i = lane + t * 32;
        if (i < IDIM) xattn[(size_t)p * IDIM + i] = xa[t] * (e[t] * inv);
    }
}

// ---------------------------------------------------------------------------
// Kernel 2 (UNCHANGED from R11 — validated): single-pass fp16 mma.m16n8k16,
// fp32 accumulate, conversion once at fill. Block 128x128, warp tile 64x32.
// ---------------------------------------------------------------------------
#define SP2 44   // uint stride per row: (44g + t) mod 32 all-distinct

__device__ __forceinline__ unsigned f16pack(float v0, float v1) {
    unsigned r;
    asm("cvt.rn.f16x2.f32 %0, %1, %2;" : "=r"(r) : "f"(v1), "f"(v0));
    return r;
}

__device__ __forceinline__ void mma_f16(float d[4],
                                        unsigned a0, unsigned a1,
                                        unsigned a2, unsigned a3,
                                        unsigned b0, unsigned b1) {
    asm("mma.sync.aligned.m16n8k16.row.col.f32.f16.f16.f32 "
        "{%0,%1,%2,%3}, {%4,%5,%6,%7}, {%8,%9}, {%0,%1,%2,%3};"
        : "+f"(d[0]), "+f"(d[1]), "+f"(d[2]), "+f"(d[3])
        : "r"(a0), "r"(a1), "r"(a2), "r"(a3), "r"(b0), "r"(b1));
}

__global__ __launch_bounds__(256, 2) void gemm_kernel(
    const float* __restrict__ A, const float* __restrict__ W,
    const float* __restrict__ bias, float* __restrict__ out)
{
    extern __shared__ unsigned smem_u[];
    unsigned* As = smem_u;
    unsigned* Bs = smem_u + 128 * SP2;

    const int bn  = blockIdx.x * 128;
    const int bm  = blockIdx.y * 128;
    const int tid = threadIdx.x;
    const int warp = tid >> 5, lane = tid & 31;
    const int wm = warp >> 2;
    const int wn = warp & 3;
    const int g  = lane >> 2;
    const int t  = lane & 3;

#pragma unroll
    for (int it = 0; it < 10; ++it) {
        int idx = tid + it * 256;
        int row = idx / 20;
        int k4  = (idx % 20) * 4;
        int c   = k4 >> 1;

        float4 a = *reinterpret_cast<const float4*>(A + (size_t)(bm + row) * IDIM + k4);
        *reinterpret_cast<uint2*>(&As[row * SP2 + c]) =
            make_uint2(f16pack(a.x, a.y), f16pack(a.z, a.w));

        float4 b = *reinterpret_cast<const float4*>(W + (size_t)(bn + row) * IDIM + k4);
        *reinterpret_cast<uint2*>(&Bs[row * SP2 + c]) =
            make_uint2(f16pack(b.x, b.y), f16pack(b.z, b.w));
    }
    __syncthreads();

    float d[4][4][4];
#pragma unroll
    for (int mt = 0; mt < 4; ++mt)
#pragma unroll
        for (int nt = 0; nt < 4; ++nt)
#pragma unroll
            for (int r = 0; r < 4; ++r) d[mt][nt][r] = 0.0f;

#pragma unroll
    for (int kc = 0; kc < 5; ++kc) {
        const int kb = kc * 8 + t;

        unsigned b0[4], b1[4];
#pragma unroll
        for (int nt = 0; nt < 4; ++nt) {
            int nr = (wn * 32 + nt * 8 + g) * SP2 + kb;
            b0[nt] = Bs[nr];
            b1[nt] = Bs[nr + 4];
        }

#pragma unroll
        for (int mt = 0; mt < 4; ++mt) {
            int r0 = (wm * 64 + mt * 16 + g) * SP2 + kb;
            unsigned a0 = As[r0];
            unsigned a1 = As[r0 + 8 * SP2];
            unsigned a2 = As[r0 + 4];
            unsigned a3 = As[r0 + 8 * SP2 + 4];
#pragma unroll
            for (int nt = 0; nt < 4; ++nt)
                mma_f16(d[mt][nt], a0, a1, a2, a3, b0[nt], b1[nt]);
        }
    }

#pragma unroll
    for (int mt = 0; mt < 4; ++mt) {
#pragma unroll
        for (int nt = 0; nt < 4; ++nt) {
            int row = bm + wm * 64 + mt * 16 + g;
            int col = bn + wn * 32 + nt * 8 + 2 * t;
            float b0 = __ldg(bias + col), b1 = __ldg(bias + col + 1);
            float2 o0 = make_float2(d[mt][nt][0] + b0, d[mt][nt][1] + b1);
            float2 o1 = make_float2(d[mt][nt][2] + b0, d[mt][nt][3] + b1);
            *reinterpret_cast<float2*>(out + (size_t)row * HDIM + col) = o0;
            *reinterpret_cast<float2*>(out + (size_t)(row + 8) * HDIM + col) = o1;
        }
    }
}

extern "C" void kernel_launch(void* const* d_in, const int* in_sizes, int n_in,
                              void* d_out, int out_size)
{
    const float* x    = (const float*)d_in[0];
    const float* y    = (const float*)d_in[1];
    const float* fc1w = (const float*)d_in[2];
    const float* fc1b = (const float*)d_in[3];
    float* out = (float*)d_out;

    float* xattn = nullptr;
    cudaGetSymbolAddress((void**)&xattn, g_xattn);

    attn_kernel<<<BT / PAIRS_PER_BLK, 256>>>(x, y, xattn);

    const int smem_bytes = 2 * 128 * SP2 * (int)sizeof(unsigned);  // 45056
    cudaFuncSetAttribute(gemm_kernel,
                         cudaFuncAttributeMaxDynamicSharedMemorySize, smem_bytes);
    gemm_kernel<<<dim3(HDIM / 128, BT / 128), 256, smem_bytes>>>(xattn, fc1w, fc1b, out);
}